// round 16
// baseline (speedup 1.0000x reference)
#include <cuda_runtime.h>
#include <cuda_fp16.h>
#include <cstdint>
#include <math.h>

#define NSITE 524288          // 32*32*32*16
#define TILE  128
#define NTILES (NSITE / TILE) // 4096
#define NT    256             // 8 warps, 32 cols each
#define GRID  148

// SMEM word (float) offsets
#define XF_OFF  0             // X frags fp16: [m][ks4][lane][4w] = 4096 words (16 KB)
#define HF_OFF  4096          // H frags fp16: [mlp][m][ks8][lane][4w] = 16384 words (64 KB)
#define SP_OFF  20480         // head partials: [mlp][4][128] = 1024 words
#define SAR_OFF 21504         // AR dots: 128 words
#define SMEM_FLOATS 21632
#define SMEM_BYTES (SMEM_FLOATS * 4)

__device__ float  g_nn[NSITE];
__device__ __half g_W1h[16384];             // [W1;W1n]*diag(weight), fp16  [256][64]
__device__ __half g_W2h[32768];             // [W2;W2n], fp16               [256][128]
__device__ __align__(16) float  g_b1ext[256];
__device__ __align__(16) float2 g_c2 [128];   // (b2, w3)
__device__ __align__(16) float2 g_c2n[128];   // (b2n, w3n)

static __device__ __forceinline__ float tanha(float x) {
    float y; asm("tanh.approx.f32 %0, %1;" : "=f"(y) : "f"(x)); return y;
}
// m16n8k16 fp16 mma, fp16 accum (2 c-regs, each half2)
static __device__ __forceinline__ void mma_f16acc(
    uint32_t& c0, uint32_t& c1,
    uint32_t a0, uint32_t a1, uint32_t a2, uint32_t a3,
    uint32_t b0, uint32_t b1)
{
    asm volatile(
        "mma.sync.aligned.m16n8k16.row.col.f16.f16.f16.f16 "
        "{%0,%1}, {%2,%3,%4,%5}, {%6,%7}, {%0,%1};"
        : "+r"(c0), "+r"(c1)
        : "r"(a0), "r"(a1), "r"(a2), "r"(a3), "r"(b0), "r"(b1));
}
static __device__ __forceinline__ uint32_t h2u(__half2 h) {
    uint32_t u; *(__half2*)&u = h; return u;
}
static __device__ __forceinline__ float2 u2f2(uint32_t u) {
    return __half22float2(*(__half2*)&u);
}

__global__ __launch_bounds__(NT, 1)
void fnn_mma_kernel(
    const float* __restrict__ x_in, const float* __restrict__ ag,
    const float* __restrict__ b3,  const float* __restrict__ b3n,
    const float* __restrict__ max_os_l,
    float* __restrict__ out_os)
{
    extern __shared__ float sm[];
    const int tid = threadIdx.x;
    const int wid = tid >> 5;       // 0..7
    const int lid = tid & 31;
    const int g   = lid >> 2;
    const int t   = lid & 3;

    const int mlp = wid >> 2;       // 0..1
    const int cg  = wid & 3;        // 32-col group within mlp
    const int nb  = cg * 32;

    const float maxos = expf(max_os_l[0]);
    const float b3v = b3[0], b3nv = b3n[0];

    // ---- persistent B fragments (fp16: 32 + 64 = 96 regs) ----
    uint32_t B1r[4][8];
    uint32_t B2r[4][16];
    #pragma unroll
    for (int j = 0; j < 4; j++) {
        const __half* wp = g_W1h + (size_t)(mlp*128 + nb + 8*j + g) * 64;
        #pragma unroll
        for (int ks = 0; ks < 4; ks++) {
            B1r[j][ks*2+0] = *(const uint32_t*)(wp + ks*16 + 2*t);
            B1r[j][ks*2+1] = *(const uint32_t*)(wp + ks*16 + 2*t + 8);
        }
        const __half* wp2 = g_W2h + (size_t)(mlp*128 + nb + 8*j + g) * 128;
        #pragma unroll
        for (int ks = 0; ks < 8; ks++) {
            B2r[j][ks*2+0] = *(const uint32_t*)(wp2 + ks*16 + 2*t);
            B2r[j][ks*2+1] = *(const uint32_t*)(wp2 + ks*16 + 2*t + 8);
        }
    }
    // bias / head constants
    float2 bv[4]; float4 cw[4];
    #pragma unroll
    for (int j = 0; j < 4; j++) {
        int c0 = nb + 8*j + 2*t;
        bv[j] = *(const float2*)(g_b1ext + mlp*128 + c0);
        cw[j] = *(const float4*)((mlp ? g_c2n : g_c2) + c0);
    }
    // staging constants
    const int cst = (tid & 15) * 4;
    const float4 ag4 = *(const float4*)(ag + cst);
    const int s_ks = cst >> 4;
    const int s_u  = (cst & 15) >> 1;
    const int s_t  = s_u & 3;
    const int s_kh = s_u >> 2;

    // ---- prefetch first tile into registers ----
    float4 vreg[8];
    int tile = blockIdx.x;
    if (tile < NTILES) {
        #pragma unroll
        for (int it = 0; it < 8; it++) {
            int row = (tid >> 4) + it * 16;
            vreg[it] = *(const float4*)(x_in + (size_t)(tile*TILE + row) * 64 + cst);
        }
    }

    for (; tile < NTILES; tile += GRID) {
        const int base = tile * TILE;

        // ---- stage X from prefetched regs + AR dot ----
        #pragma unroll
        for (int it = 0; it < 8; it++) {
            int row = (tid >> 4) + it * 16;
            float4 v = vreg[it];
            float pr = v.x*ag4.x + v.y*ag4.y + v.z*ag4.z + v.w*ag4.w;
            pr += __shfl_xor_sync(0xffffffffu, pr, 8);
            pr += __shfl_xor_sync(0xffffffffu, pr, 4);
            pr += __shfl_xor_sync(0xffffffffu, pr, 2);
            pr += __shfl_xor_sync(0xffffffffu, pr, 1);
            if ((tid & 15) == 0) sm[SAR_OFF + row] = pr;
            int m = row >> 4, gg = row & 7, hi = (row >> 3) & 1;
            int r = hi + 2*s_kh;
            float* p = sm + XF_OFF + m*512 + s_ks*128 + (gg*4 + s_t)*4 + r;
            *(__half2*)(p)     = __floats2half2_rn(v.x, v.y);
            *(__half2*)(p + 4) = __floats2half2_rn(v.z, v.w);
        }
        __syncthreads();   // S1

        // ---- prefetch next tile (overlaps GEMM1/GEMM2) ----
        {
            int nt_ = tile + GRID;
            if (nt_ < NTILES) {
                #pragma unroll
                for (int it = 0; it < 8; it++) {
                    int row = (tid >> 4) + it * 16;
                    vreg[it] = *(const float4*)(x_in + (size_t)(nt_*TILE + row) * 64 + cst);
                }
            }
        }

        // ---- GEMM1: H = tanh(X @ W1'^T + b1), K=64, 4 j-chains, fp16 acc ----
        #pragma unroll
        for (int m = 0; m < 8; m++) {
            const float* ap = sm + XF_OFF + m*512 + lid*4;
            uint4 A[4];
            #pragma unroll
            for (int ks = 0; ks < 4; ks++) A[ks] = *(const uint4*)(ap + ks*128);
            uint32_t acc[4][2];
            #pragma unroll
            for (int j = 0; j < 4; j++) { acc[j][0] = 0u; acc[j][1] = 0u; }
            #pragma unroll
            for (int ks = 0; ks < 4; ks++) {
                #pragma unroll
                for (int j = 0; j < 4; j++)
                    mma_f16acc(acc[j][0], acc[j][1],
                               A[ks].x,A[ks].y,A[ks].z,A[ks].w,
                               B1r[j][ks*2], B1r[j][ks*2+1]);
            }
            // unpack: acc[j][0] = (c0,c1) rows g; acc[j][1] = (c2,c3) rows g+8
            #pragma unroll
            for (int jp = 0; jp < 2; jp++) {
                const int j0 = 2*jp, j1 = 2*jp + 1;
                float2 p0 = u2f2(acc[j0][0]), q0 = u2f2(acc[j0][1]);
                float2 p1 = u2f2(acc[j1][0]), q1 = u2f2(acc[j1][1]);
                uint4 hw;
                hw.x = h2u(__floats2half2_rn(tanha(p0.x + bv[j0].x),
                                             tanha(p0.y + bv[j0].y)));
                hw.y = h2u(__floats2half2_rn(tanha(q0.x + bv[j0].x),
                                             tanha(q0.y + bv[j0].y)));
                hw.z = h2u(__floats2half2_rn(tanha(p1.x + bv[j1].x),
                                             tanha(p1.y + bv[j1].y)));
                hw.w = h2u(__floats2half2_rn(tanha(q1.x + bv[j1].x),
                                             tanha(q1.y + bv[j1].y)));
                *(uint4*)(sm + HF_OFF + mlp*8192 + m*1024 + (2*cg + jp)*128 + lid*4) = hw;
            }
        }
        __syncthreads();   // S2

        // ---- GEMM2: head partials, K=128, 4 j-chains, fp16 acc ----
        #pragma unroll
        for (int m = 0; m < 8; m++) {
            const float* ap = sm + HF_OFF + mlp*8192 + m*1024 + lid*4;
            uint32_t acc[4][2];
            #pragma unroll
            for (int j = 0; j < 4; j++) { acc[j][0] = 0u; acc[j][1] = 0u; }
            #pragma unroll
            for (int half_ = 0; half_ < 2; half_++) {
                uint4 A[4];
                #pragma unroll
                for (int ks = 0; ks < 4; ks++)
                    A[ks] = *(const uint4*)(ap + (half_*4 + ks)*128);
                #pragma unroll
                for (int ks = 0; ks < 4; ks++) {
                    const int kk = half_*4 + ks;
                    #pragma unroll
                    for (int j = 0; j < 4; j++)
                        mma_f16acc(acc[j][0], acc[j][1],
                                   A[ks].x,A[ks].y,A[ks].z,A[ks].w,
                                   B2r[j][kk*2], B2r[j][kk*2+1]);
                }
            }
            float sum0 = 0.f, sum1 = 0.f;
            #pragma unroll
            for (int j = 0; j < 4; j++) {
                float2 p = u2f2(acc[j][0]);   // rows g:   (c0,c1)
                float2 q = u2f2(acc[j][1]);   // rows g+8: (c2,c3)
                sum0 += tanha(p.x + cw[j].x)*cw[j].y + tanha(p.y + cw[j].z)*cw[j].w;
                sum1 += tanha(q.x + cw[j].x)*cw[j].y + tanha(q.y + cw[j].z)*cw[j].w;
            }
            sum0 += __shfl_xor_sync(0xffffffffu, sum0, 1);
            sum0 += __shfl_xor_sync(0xffffffffu, sum0, 2);
            sum1 += __shfl_xor_sync(0xffffffffu, sum1, 1);
            sum1 += __shfl_xor_sync(0xffffffffu, sum1, 2);
            if (t == 0) {
                sm[SP_OFF + mlp*512 + cg*128 + m*16 + g]     = sum0;
                sm[SP_OFF + mlp*512 + cg*128 + m*16 + g + 8] = sum1;
            }
        }
        __syncthreads();   // S3

        // ---- heads: both mlps in parallel (all 256 threads) ----
        {
            int hm   = tid >> 7;       // 0: os, 1: nn
            int site = tid & 127;
            float s = 0.f;
            #pragma unroll
            for (int p = 0; p < 4; p++) s += sm[SP_OFF + hm*512 + p*128 + site];
            float val = tanhf(s + (hm ? b3nv : b3v)) * maxos;
            if (hm == 0) out_os[base + site] = val + sm[SAR_OFF + site];
            else         g_nn  [base + site] = val;
        }
        __syncthreads();   // S4
    }
}

// ---- prep: fold weight into W1, fp16-convert B matrices, pack constants ----
__global__ void fnn_prep_kernel(
    const float* __restrict__ W1,  const float* __restrict__ W1n,
    const float* __restrict__ weight,
    const float* __restrict__ W2,  const float* __restrict__ W2n,
    const float* __restrict__ b1,  const float* __restrict__ b1n,
    const float* __restrict__ b2,  const float* __restrict__ w3,
    const float* __restrict__ b2n, const float* __restrict__ w3n)
{
    int idx = blockIdx.x * blockDim.x + threadIdx.x;   // 32768 threads
    if (idx < 16384) {
        int n = idx >> 6, k = idx & 63;
        float v = (n < 128 ? W1[n * 64 + k] : W1n[(n - 128) * 64 + k]) * weight[k];
        g_W1h[idx] = __float2half_rn(v);
    }
    g_W2h[idx] = __float2half_rn(idx < 16384 ? W2[idx] : W2n[idx - 16384]);
    if (idx < 128) {
        g_b1ext[idx]       = b1[idx];
        g_b1ext[128 + idx] = b1n[idx];
        g_c2 [idx] = make_float2(b2[idx],  w3[idx]);
        g_c2n[idx] = make_float2(b2n[idx], w3n[idx]);
    }
}

// ---- stencil + sigma ----
__global__ void fnn_stencil_kernel(const float* __restrict__ sigma_l,
                                   float* __restrict__ out)
{
    int idx = blockIdx.x * blockDim.x + threadIdx.x;
    if (idx >= NSITE) return;
    const int ib = idx & 15;
    const int iz = (idx >> 4)  & 31;
    const int iy = (idx >> 9)  & 31;
    const int ix = (idx >> 14) & 31;
    const int xm = (ix + 31) & 31, xp = (ix + 1) & 31;
    const int ym = (iy + 31) & 31, yp = (iy + 1) & 31;
    const int zm = (iz + 31) & 31, zp = (iz + 1) & 31;
#define FNN_I(a, b, c) ((((((a) << 5) + (b)) << 5) + (c)) * 16 + ib)
    float s =
        g_nn[FNN_I(xm, iy, zm)] + g_nn[FNN_I(xm, iy, zp)] +
        g_nn[FNN_I(xp, iy, zm)] + g_nn[FNN_I(xp, iy, zp)] +
        g_nn[FNN_I(ix, ym, zm)] + g_nn[FNN_I(ix, ym, zp)] +
        g_nn[FNN_I(ix, yp, zm)] + g_nn[FNN_I(ix, yp, zp)];
#undef FNN_I
    out[idx] += 0.125f * s;
    out[NSITE + idx] = expf(sigma_l[0]);
}

extern "C" void kernel_launch(void* const* d_in, const int* in_sizes, int n_in,
                              void* d_out, int out_size)
{
    const float* x_in     = (const float*)d_in[0];
    const float* weight   = (const float*)d_in[1];
    const float* ag       = (const float*)d_in[2];
    const float* W1       = (const float*)d_in[3];
    const float* b1       = (const float*)d_in[4];
    const float* W2       = (const float*)d_in[5];
    const float* b2       = (const float*)d_in[6];
    const float* W3       = (const float*)d_in[7];
    const float* b3       = (const float*)d_in[8];
    const float* W1n      = (const float*)d_in[9];
    const float* b1n      = (const float*)d_in[10];
    const float* W2n      = (const float*)d_in[11];
    const float* b2n      = (const float*)d_in[12];
    const float* W3n      = (const float*)d_in[13];
    const float* b3n      = (const float*)d_in[14];
    const float* max_os_l = (const float*)d_in[15];
    const float* sigma_l  = (const float*)d_in[16];
    float* out = (float*)d_out;

    fnn_prep_kernel<<<128, 256>>>(W1, W1n, weight, W2, W2n,
                                  b1, b1n, b2, W3, b2n, W3n);

    cudaFuncSetAttribute(fnn_mma_kernel,
                         cudaFuncAttributeMaxDynamicSharedMemorySize, SMEM_BYTES);
    fnn_mma_kernel<<<GRID, NT, SMEM_BYTES>>>(
        x_in, ag, b3, b3n, max_os_l, out);

    fnn_stencil_kernel<<<NSITE / 256, 256>>>(sigma_l, out);
}